// round 13
// baseline (speedup 1.0000x reference)
#include <cuda_runtime.h>
#include <cuda_fp16.h>
#include <cstdint>

// ============================================================================
// out[64,8] = exp(-1e-4 * ||x_b - c_j||^2) @ fc_w.T + fc_b
//   x: [64, 65536] f32, centers: [500, 65536] f32
// K1: fp16 GEMM, fp16 accumulators (m32n32 warp tiles, occ 4, one wave).
//     grid 512 = 256 kgroups(k256) x 2 m-halves. SHUFFLE-FREE convert path:
//     per-lane dot4 norms staged to smem (f16), reduced by warps 0-3 in
//     parallel with MMA; x norms predicated to 1/4 of sub-phases. Convert
//     loops are pure LDG->CVT->STS (max MLP).
// K2: reduce partials over S + norms -> rbf[b][c].   K3: fc head.
// Base sm_100 only (harness compiles compute_100: no tcgen05).
// ============================================================================

#define GAMMA_F 1e-4f

static constexpr int S_SPLIT = 256;   // partial granularity (k256 chunks)
static constexpr int NB      = 64;
static constexpr int NCPAD   = 512;

// -------- scratch --------
__device__ __half g_parth[(size_t)NCPAD * S_SPLIT * NB];  // [c][s][b] 16 MB
__device__ float  g_csq_p[(size_t)NCPAD * 512];           // [c][kg*2+kc]
__device__ float  g_xsq_p[(size_t)NB    * 512];           // [b][kg*2+kc]
__device__ float  g_rbf  [(size_t)NB * NCPAD];            // [b][c]

// -------- helpers --------
__device__ __forceinline__ uint32_t smem_u32(const void* p) {
    uint32_t a;
    asm("{ .reg .u64 t; cvta.to.shared.u64 t, %1; cvt.u32.u64 %0, t; }" : "=r"(a) : "l"(p));
    return a;
}
// x tile: 64 rows x 128 k f16 (16KB); atoms 8 rows x 64 f16
__device__ __forceinline__ uint32_t roffx(int row, int k) {
    uint32_t r7 = (uint32_t)(row & 7);
    return (((uint32_t)(k >> 6) * 8u + (uint32_t)(row >> 3)) << 10)
         + r7 * 128u + (((uint32_t)(k & 63) * 2u) ^ (r7 << 4));
}
// c tile: 128 rows x 128 k f16 (32KB); 16 atom-rows per 64-k block
__device__ __forceinline__ uint32_t roffc(int row, int k) {
    uint32_t r7 = (uint32_t)(row & 7);
    return (((uint32_t)(k >> 6) * 16u + (uint32_t)(row >> 3)) << 10)
         + r7 * 128u + (((uint32_t)(k & 63) * 2u) ^ (r7 << 4));
}
__device__ __forceinline__ uint32_t pack_h2(float a, float b) {
    __half2 t = __floats2half2_rn(a, b);
    return *reinterpret_cast<uint32_t*>(&t);
}
__device__ __forceinline__ void ldsm_x4(uint32_t* r, uint32_t addr) {
    asm volatile("ldmatrix.sync.aligned.m8n8.x4.shared.b16 {%0,%1,%2,%3}, [%4];"
                 : "=r"(r[0]), "=r"(r[1]), "=r"(r[2]), "=r"(r[3]) : "r"(addr));
}
// f16 x f16 -> f16 acc (2 regs)
__device__ __forceinline__ void mma_f16(uint32_t* d, const uint32_t* a, const uint32_t* b) {
    asm volatile("mma.sync.aligned.m16n8k16.row.col.f16.f16.f16.f16 "
                 "{%0,%1}, {%2,%3,%4,%5}, {%6,%7}, {%0,%1};"
                 : "+r"(d[0]), "+r"(d[1])
                 : "r"(a[0]), "r"(a[1]), "r"(a[2]), "r"(a[3]), "r"(b[0]), "r"(b[1]));
}
__device__ __forceinline__ float dot4(float4 v) {
    return v.x * v.x + v.y * v.y + v.z * v.z + v.w * v.w;
}
__device__ __forceinline__ float warp_sum(float v) {
    #pragma unroll
    for (int d = 16; d > 0; d >>= 1) v += __shfl_xor_sync(0xffffffffu, v, d);
    return v;
}

// -------- SMEM: x 16KB | c 32KB | sq stage 8KB  (57344 B -> occ 4) --------
static constexpr int SMEM_X     = 0;
static constexpr int SMEM_C     = 16384;
static constexpr int SMEM_SQ    = 49152;
static constexpr int SMEM_TOTAL = 57344;

// ============================================================================
// Kernel 1
// ============================================================================
__global__ void __launch_bounds__(256, 4)
svm_main_kernel(const float* __restrict__ x, const float* __restrict__ centers) {
    extern __shared__ char smem[];
    const uint32_t smem_base = smem_u32(smem);
    __half* stage = reinterpret_cast<__half*>(smem + SMEM_SQ);   // [128][32]
    const int tid = threadIdx.x;
    const int wid = tid >> 5;
    const int lid = tid & 31;
    const int kg  = blockIdx.x >> 1;       // k-group (k256)
    const int mh  = blockIdx.x & 1;        // m-half (rows mh*256..)

    // MMA lane constants: warp tile m32 x n32, 8 warps = 4(M) x 2(N)
    const int mg = wid & 3;
    const int ng = wid >> 2;
    const int sel = lid >> 3;
    const int l7  = lid & 7;
    const int a_row = mg * 32 + l7 + (sel & 1) * 8;
    const int a_kd  = (sel >> 1) * 8;
    const int b_row = ng * 32 + l7 + (sel >> 1) * 8;
    const int b_kd  = (sel & 1) * 8;
    const uint32_t xb = smem_base + SMEM_X;
    const uint32_t cb = smem_base + SMEM_C;

    for (int t = 0; t < 2; t++) {
        uint32_t acc[2][4][2];             // f16x2 accumulators (16 regs)
        #pragma unroll
        for (int mi = 0; mi < 2; mi++)
            #pragma unroll
            for (int ni = 0; ni < 4; ni++) { acc[mi][ni][0] = 0u; acc[mi][ni][1] = 0u; }

        for (int kc = 0; kc < 2; kc++) {
            const size_t k0 = (size_t)kg * 256 + kc * 128;
            __syncthreads();               // prior MMA + stage reads done

            // ---- convert x sub-chunk: warp w -> rows 8w..8w+7, coalesced ----
            {
                char* tile = smem + SMEM_X;
                const bool do_xsq = (mh == 0) && (t == 0);   // warp-uniform
                #pragma unroll
                for (int h = 0; h < 2; h++) {
                    float4 v[4];
                    const int rb = wid * 8 + h * 4;
                    #pragma unroll
                    for (int r = 0; r < 4; r++)
                        v[r] = reinterpret_cast<const float4*>(
                                   x + (size_t)(rb + r) * 65536 + k0)[lid];
                    #pragma unroll
                    for (int r = 0; r < 4; r++)
                        *reinterpret_cast<uint2*>(tile + roffx(rb + r, 4 * lid)) =
                            make_uint2(pack_h2(v[r].x, v[r].y), pack_h2(v[r].z, v[r].w));
                    if (do_xsq) {
                        #pragma unroll
                        for (int r = 0; r < 4; r++) {
                            float sq = warp_sum(dot4(v[r]));
                            if (lid == 0)
                                g_xsq_p[(size_t)(rb + r) * 512 + kg * 2 + kc] = sq;
                        }
                    }
                }
            }
            // ---- convert c tile: warp w -> rows 16w..16w+15; norms staged ----
            {
                char* tile = smem + SMEM_C;
                const int gbase = mh * 256 + t * 128;
                #pragma unroll
                for (int h = 0; h < 4; h++) {
                    float4 v[4];
                    const int rb = wid * 16 + h * 4;
                    #pragma unroll
                    for (int r = 0; r < 4; r++) {
                        int gr = gbase + rb + r;
                        int grc = gr < 500 ? gr : 499;
                        v[r] = reinterpret_cast<const float4*>(
                                   centers + (size_t)grc * 65536 + k0)[lid];
                    }
                    #pragma unroll
                    for (int r = 0; r < 4; r++) {
                        int gr = gbase + rb + r;
                        bool ok = gr < 500;
                        uint2 pk = ok ? make_uint2(pack_h2(v[r].x, v[r].y),
                                                   pack_h2(v[r].z, v[r].w))
                                      : make_uint2(0u, 0u);
                        *reinterpret_cast<uint2*>(tile + roffc(rb + r, 4 * lid)) = pk;
                        stage[(rb + r) * 32 + lid] = __float2half(ok ? dot4(v[r]) : 0.f);
                    }
                }
            }
            __syncthreads();

            // ---- warps 0-3: reduce staged c norms (shuffle-free), then MMA ----
            if (tid < 128) {
                const int row = tid;
                const __half2* p2 = reinterpret_cast<const __half2*>(stage + row * 32);
                float sum = 0.f;
                #pragma unroll
                for (int i = 0; i < 16; i++) {
                    float2 f = __half22float2(p2[i]);
                    sum += f.x + f.y;
                }
                const int gr = mh * 256 + t * 128 + row;
                if (gr < 500) g_csq_p[(size_t)gr * 512 + kg * 2 + kc] = sum;
            }

            // ---- MMA: m32n32 over k128, f16 acc ----
            #pragma unroll 8
            for (int kk = 0; kk < 128; kk += 16) {
                uint32_t af[2][4], bf[2][4];
                ldsm_x4(af[0], cb + roffc(a_row,      kk + a_kd));
                ldsm_x4(af[1], cb + roffc(a_row + 16, kk + a_kd));
                ldsm_x4(bf[0], xb + roffx(b_row,      kk + b_kd));
                ldsm_x4(bf[1], xb + roffx(b_row + 16, kk + b_kd));
                #pragma unroll
                for (int mi = 0; mi < 2; mi++)
                    #pragma unroll
                    for (int ni = 0; ni < 4; ni++)
                        mma_f16(acc[mi][ni], af[mi], &bf[ni >> 1][(ni & 1) * 2]);
            }
        }

        // ---- epilogue: f16 acc -> g_parth directly ----
        {
            const int rbase = mh * 256 + t * 128 + mg * 32;
            uint32_t* gp = reinterpret_cast<uint32_t*>(g_parth);
            #pragma unroll
            for (int mi = 0; mi < 2; mi++) {
                #pragma unroll
                for (int ni = 0; ni < 4; ni++) {
                    const int col = ng * 32 + ni * 8 + (lid & 3) * 2;
                    const int r0 = rbase + mi * 16 + (lid >> 2);
                    gp[(((size_t)r0       * S_SPLIT + kg) << 5) + (col >> 1)] = acc[mi][ni][0];
                    gp[(((size_t)(r0 + 8) * S_SPLIT + kg) << 5) + (col >> 1)] = acc[mi][ni][1];
                }
            }
        }
    }
}

// ============================================================================
// Kernel 2: reduce partials over S=256 + finalize norms -> rbf[b][c]
// ============================================================================
__global__ void __launch_bounds__(512)
svm_rbf_kernel() {
    __shared__ float red [16][NB];
    __shared__ float redx[8][NB];
    __shared__ float s_csq;
    const int c   = blockIdx.x;          // 0..499
    const int tid = threadIdx.x;         // 512
    const int sp   = tid >> 5;           // 0..15 (16 s-values each)
    const int lane = tid & 31;

    // cross partials: coalesced half2 stream
    {
        const __half2* p =
            reinterpret_cast<const __half2*>(g_parth + ((size_t)c * S_SPLIT + sp * 16) * NB) + lane;
        float2 a = make_float2(0.f, 0.f);
        #pragma unroll
        for (int i = 0; i < 16; i++) {
            float2 f = __half22float2(p[(size_t)i * 32]);
            a.x += f.x; a.y += f.y;
        }
        red[sp][2 * lane]     = a.x;
        red[sp][2 * lane + 1] = a.y;
    }
    // xsq: 8 threads per batch row (512 sub-chunk values)
    {
        const int b = tid >> 3, q = tid & 7;
        const float4* xp = reinterpret_cast<const float4*>(g_xsq_p + (size_t)b * 512 + q * 64);
        float v = 0.f;
        #pragma unroll
        for (int i = 0; i < 16; i++) {
            float4 t = xp[i];
            v += t.x + t.y + t.z + t.w;
        }
        redx[q][b] = v;
    }
    // csq: warp 0 reads 512 floats
    if (tid < 32) {
        const float4* cp = reinterpret_cast<const float4*>(g_csq_p + (size_t)c * 512);
        float4 t0 = cp[tid], t1 = cp[tid + 32], t2 = cp[tid + 64], t3 = cp[tid + 96];
        float v = t0.x + t0.y + t0.z + t0.w + t1.x + t1.y + t1.z + t1.w
                + t2.x + t2.y + t2.z + t2.w + t3.x + t3.y + t3.z + t3.w;
        #pragma unroll
        for (int d = 16; d > 0; d >>= 1) v += __shfl_xor_sync(0xffffffffu, v, d);
        if (tid == 0) s_csq = v;
    }
    __syncthreads();
    if (tid < NB) {
        float cross = 0.f, xs = 0.f;
        #pragma unroll
        for (int i = 0; i < 16; i++) cross += red[i][tid];
        #pragma unroll
        for (int i = 0; i < 8; i++) xs += redx[i][tid];
        float dist = xs - 2.0f * cross + s_csq;
        g_rbf[(size_t)tid * NCPAD + c] = expf(-GAMMA_F * dist);   // [b][c]
    }
}

// ============================================================================
// Kernel 3: out[b][i] = sum_c rbf[b][c] * fc_w[i][c] + fc_b[i]
// ============================================================================
__global__ void __launch_bounds__(128)
svm_fc_kernel(const float* __restrict__ fc_w,
              const float* __restrict__ fc_b,
              float* __restrict__ out) {
    __shared__ float w4[4];
    const int b = blockIdx.x >> 3;
    const int i = blockIdx.x & 7;
    const int t = threadIdx.x;
    const float* rr = g_rbf + (size_t)b * NCPAD;
    const float* ww = fc_w + i * 500;
    float acc = 0.f;
    #pragma unroll
    for (int q = 0; q < 4; q++) {
        int c = t + q * 128;
        if (c < 500) acc += rr[c] * ww[c];
    }
    acc = warp_sum(acc);
    if ((t & 31) == 0) w4[t >> 5] = acc;
    __syncthreads();
    if (t == 0) out[b * 8 + i] = w4[0] + w4[1] + w4[2] + w4[3] + fc_b[i];
}

// ============================================================================
extern "C" void kernel_launch(void* const* d_in, const int* in_sizes, int n_in,
                              void* d_out, int out_size) {
    const float* x       = (const float*)d_in[0];
    const float* centers = (const float*)d_in[1];
    const float* fc_w    = (const float*)d_in[2];
    const float* fc_b    = (const float*)d_in[3];
    float* out = (float*)d_out;

    cudaFuncSetAttribute(svm_main_kernel, cudaFuncAttributeMaxDynamicSharedMemorySize, SMEM_TOTAL);

    svm_main_kernel<<<512, 256, SMEM_TOTAL>>>(x, centers);
    svm_rbf_kernel<<<500, 512>>>();
    svm_fc_kernel<<<512, 128>>>(fc_w, fc_b, out);
}

// round 14
// speedup vs baseline: 1.4409x; 1.4409x over previous
#include <cuda_runtime.h>
#include <cuda_bf16.h>
#include <cuda_fp16.h>
#include <cstdint>

// ============================================================================
// out[64,8] = exp(-1e-4 * ||x_b - c_j||^2) @ fc_w.T + fc_b
//   x: [64, 65536] f32, centers: [500, 65536] f32
// K1 (= round-10 best, 52.8us): split-K x split-M, grid 512, 256 thr, 48KB,
//     occ 4, one wave. bf16 mma.sync, f32 acc, k-split across warp groups +
//     smem exchange. f16 partials [c][s=256][b].
// K0: finalize norms once (576 warp-rows) -> cs[512], xs[64].
// K2: ONLY the coalesced partial reduction + norm lookups -> rbf[b][c].
//     (the old per-block xsq re-reduction was ~15us of redundant uncoalesced
//      L1 wavefronts, 500x duplicated -- removed.)
// K3: fc head, grid 512.
// Base sm_100 only (harness compiles compute_100: no tcgen05).
// ============================================================================

#define GAMMA_F 1e-4f

static constexpr int S_SPLIT = 256;   // K chunks
static constexpr int KC      = 256;   // K per chunk
static constexpr int NB      = 64;    // batch
static constexpr int NCPAD   = 512;
static constexpr int NSB     = 8;     // 32-row center sub-blocks per CTA

// -------- scratch --------
__device__ __half g_parth[(size_t)NCPAD * S_SPLIT * NB];  // [c][s][b] 16 MB f16
__device__ float  g_csq_p[(size_t)NCPAD * S_SPLIT];
__device__ float  g_xsq_p[(size_t)NB    * S_SPLIT];       // [b][s]
__device__ float  g_cs   [NCPAD];
__device__ float  g_xs   [NB];
__device__ float  g_rbf  [(size_t)NB * NCPAD];            // [b][c]

// -------- helpers --------
__device__ __forceinline__ uint32_t smem_u32(const void* p) {
    uint32_t a;
    asm("{ .reg .u64 t; cvta.to.shared.u64 t, %1; cvt.u32.u64 %0, t; }" : "=r"(a) : "l"(p));
    return a;
}
// 64-row tile (x): atoms 8 rows x 64 bf16; 8 atom-rows per 64-k block
__device__ __forceinline__ uint32_t roff64(int row, int k) {
    uint32_t r7 = (uint32_t)(row & 7);
    return (((uint32_t)(k >> 6) * 8u + (uint32_t)(row >> 3)) << 10)
         + r7 * 128u + (((uint32_t)(k & 63) * 2u) ^ (r7 << 4));
}
// 32-row tile (c): 4 atom-rows per 64-k block
__device__ __forceinline__ uint32_t roff32(int row, int k) {
    uint32_t r7 = (uint32_t)(row & 7);
    return (((uint32_t)(k >> 6) * 4u + (uint32_t)(row >> 3)) << 10)
         + r7 * 128u + (((uint32_t)(k & 63) * 2u) ^ (r7 << 4));
}
__device__ __forceinline__ uint32_t pack_bf16x2(float a, float b) {
    __nv_bfloat162 t = __floats2bfloat162_rn(a, b);
    return *reinterpret_cast<uint32_t*>(&t);
}
__device__ __forceinline__ void ldsm_x4(uint32_t* r, uint32_t addr) {
    asm volatile("ldmatrix.sync.aligned.m8n8.x4.shared.b16 {%0,%1,%2,%3}, [%4];"
                 : "=r"(r[0]), "=r"(r[1]), "=r"(r[2]), "=r"(r[3]) : "r"(addr));
}
__device__ __forceinline__ void mma_bf16(float* d, const uint32_t* a, const uint32_t* b) {
    asm volatile("mma.sync.aligned.m16n8k16.row.col.f32.bf16.bf16.f32 "
                 "{%0,%1,%2,%3}, {%4,%5,%6,%7}, {%8,%9}, {%0,%1,%2,%3};"
                 : "+f"(d[0]), "+f"(d[1]), "+f"(d[2]), "+f"(d[3])
                 : "r"(a[0]), "r"(a[1]), "r"(a[2]), "r"(a[3]), "r"(b[0]), "r"(b[1]));
}
__device__ __forceinline__ float dot4(float4 v) {
    return v.x * v.x + v.y * v.y + v.z * v.z + v.w * v.w;
}
__device__ __forceinline__ float warp_sum(float v) {
    #pragma unroll
    for (int d = 16; d > 0; d >>= 1) v += __shfl_xor_sync(0xffffffffu, v, d);
    return v;
}

// -------- SMEM: x 32KB | c 16KB (MMA-idle: acc-exchange scratch 8KB) --------
static constexpr int SMEM_X     = 0;
static constexpr int SMEM_C     = 32768;
static constexpr int SMEM_TOTAL = 49152;

// ============================================================================
// Kernel 1  (round-10 best, verbatim)
// ============================================================================
__global__ void __launch_bounds__(256, 4)
svm_main_kernel(const float* __restrict__ x, const float* __restrict__ centers) {
    extern __shared__ char smem[];
    const uint32_t smem_base = smem_u32(smem);
    const int tid = threadIdx.x;
    const int wid = tid >> 5;
    const int lid = tid & 31;
    const int s   = blockIdx.x >> 1;       // k-chunk
    const int mh  = blockIdx.x & 1;        // m-half (center rows mh*256..)
    const size_t k0 = (size_t)s * KC;

    const int kA = 4 * lid, kB = 128 + 4 * lid;

    // ---- prologue: convert x chunk; warp w -> rows 8w..8w+7, coalesced ----
    {
        char* tile = smem + SMEM_X;
        #pragma unroll
        for (int q = 0; q < 8; q += 2) {
            const int r0 = wid * 8 + q, r1 = r0 + 1;
            const float4* g0 = reinterpret_cast<const float4*>(x + (size_t)r0 * 65536 + k0);
            const float4* g1 = reinterpret_cast<const float4*>(x + (size_t)r1 * 65536 + k0);
            float4 a0 = g0[lid], b0 = g0[lid + 32];
            float4 a1 = g1[lid], b1 = g1[lid + 32];
            *reinterpret_cast<uint2*>(tile + roff64(r0, kA)) =
                make_uint2(pack_bf16x2(a0.x, a0.y), pack_bf16x2(a0.z, a0.w));
            *reinterpret_cast<uint2*>(tile + roff64(r0, kB)) =
                make_uint2(pack_bf16x2(b0.x, b0.y), pack_bf16x2(b0.z, b0.w));
            *reinterpret_cast<uint2*>(tile + roff64(r1, kA)) =
                make_uint2(pack_bf16x2(a1.x, a1.y), pack_bf16x2(a1.z, a1.w));
            *reinterpret_cast<uint2*>(tile + roff64(r1, kB)) =
                make_uint2(pack_bf16x2(b1.x, b1.y), pack_bf16x2(b1.z, b1.w));
            float s0 = warp_sum(dot4(a0) + dot4(b0));
            float s1 = warp_sum(dot4(a1) + dot4(b1));
            if (mh == 0 && lid == 0) {
                g_xsq_p[(size_t)r0 * S_SPLIT + s] = s0;
                g_xsq_p[(size_t)r1 * S_SPLIT + s] = s1;
            }
        }
    }

    const int khalf = wid >> 2;            // 0: k 0..127, 1: k 128..255
    const int j4    = wid & 3;
    const int nbase = j4 * 16;
    const int kbase = khalf * 128;
    const int sel = lid >> 3;
    const int l7  = lid & 7;
    const int a_row = l7 + (sel & 1) * 8;
    const int a_kd  = (sel >> 1) * 8;
    const int b_row = nbase + l7 + (sel >> 1) * 8;
    const int b_kd  = (sel & 1) * 8;
    const uint32_t xb = smem_base + SMEM_X;
    const uint32_t cb = smem_base + SMEM_C;
    float* scratch = reinterpret_cast<float*>(smem + SMEM_C);   // overlaid

    for (int sb = 0; sb < NSB; sb++) {
        __syncthreads();   // prev MMA + scratch reads done -> c region free

        // ---- convert center sub-block (32 rows; warp w -> rows 4w..4w+3) ----
        {
            char* tile = smem + SMEM_C;
            const int gbase = mh * 256 + sb * 32;
            #pragma unroll
            for (int q = 0; q < 4; q += 2) {
                const int r0 = wid * 4 + q, r1 = r0 + 1;
                const int gr0 = gbase + r0, gr1 = gbase + r1;
                const float4 z = make_float4(0.f, 0.f, 0.f, 0.f);
                float4 a0, b0, a1, b1;
                if (gr0 < 500) {
                    const float4* g0 =
                        reinterpret_cast<const float4*>(centers + (size_t)gr0 * 65536 + k0);
                    a0 = g0[lid]; b0 = g0[lid + 32];
                } else { a0 = z; b0 = z; }
                if (gr1 < 500) {
                    const float4* g1 =
                        reinterpret_cast<const float4*>(centers + (size_t)gr1 * 65536 + k0);
                    a1 = g1[lid]; b1 = g1[lid + 32];
                } else { a1 = z; b1 = z; }
                *reinterpret_cast<uint2*>(tile + roff32(r0, kA)) =
                    make_uint2(pack_bf16x2(a0.x, a0.y), pack_bf16x2(a0.z, a0.w));
                *reinterpret_cast<uint2*>(tile + roff32(r0, kB)) =
                    make_uint2(pack_bf16x2(b0.x, b0.y), pack_bf16x2(b0.z, b0.w));
                *reinterpret_cast<uint2*>(tile + roff32(r1, kA)) =
                    make_uint2(pack_bf16x2(a1.x, a1.y), pack_bf16x2(a1.z, a1.w));
                *reinterpret_cast<uint2*>(tile + roff32(r1, kB)) =
                    make_uint2(pack_bf16x2(b1.x, b1.y), pack_bf16x2(b1.z, b1.w));
                float s0 = warp_sum(dot4(a0) + dot4(b0));
                float s1 = warp_sum(dot4(a1) + dot4(b1));
                if (lid == 0) {
                    if (gr0 < 500) g_csq_p[(size_t)gr0 * S_SPLIT + s] = s0;
                    if (gr1 < 500) g_csq_p[(size_t)gr1 * S_SPLIT + s] = s1;
                }
            }
        }
        __syncthreads();

        // ---- MMA: warp tile m32 x n16 over its 128-k half ----
        float acc[16];
        #pragma unroll
        for (int i = 0; i < 16; i++) acc[i] = 0.f;

        #pragma unroll 8
        for (int kk = 0; kk < 128; kk += 16) {
            uint32_t af0[4], af1[4], bf[4];
            ldsm_x4(af0, cb + roff32(a_row,      kbase + kk + a_kd));
            ldsm_x4(af1, cb + roff32(16 + a_row, kbase + kk + a_kd));
            ldsm_x4(bf,  xb + roff64(b_row,      kbase + kk + b_kd));
            mma_bf16(acc + 0,  af0, bf);
            mma_bf16(acc + 4,  af0, bf + 2);
            mma_bf16(acc + 8,  af1, bf);
            mma_bf16(acc + 12, af1, bf + 2);
        }
        __syncthreads();   // all ldsm reads of c tile done -> scratch writable

        // ---- k-half exchange: warps 4-7 publish, warps 0-3 combine+store ----
        if (khalf == 1) {
            float4* dst = reinterpret_cast<float4*>(scratch) + (j4 * 32 + lid) * 4;
            dst[0] = make_float4(acc[0],  acc[1],  acc[2],  acc[3]);
            dst[1] = make_float4(acc[4],  acc[5],  acc[6],  acc[7]);
            dst[2] = make_float4(acc[8],  acc[9],  acc[10], acc[11]);
            dst[3] = make_float4(acc[12], acc[13], acc[14], acc[15]);
        }
        __syncthreads();
        if (khalf == 0) {
            const float4* src = reinterpret_cast<const float4*>(scratch) + (j4 * 32 + lid) * 4;
            #pragma unroll
            for (int i4 = 0; i4 < 4; i4++) {
                float4 v = src[i4];
                acc[4 * i4 + 0] += v.x; acc[4 * i4 + 1] += v.y;
                acc[4 * i4 + 2] += v.z; acc[4 * i4 + 3] += v.w;
            }
            const int r0 = mh * 256 + sb * 32 + (lid >> 2);
            const int c0 = nbase + (lid & 3) * 2;
            #pragma unroll
            for (int mi = 0; mi < 2; mi++) {
                #pragma unroll
                for (int ni = 0; ni < 2; ni++) {
                    const int col = c0 + 8 * ni;
                    const float* a4 = acc + mi * 8 + ni * 4;
                    __half* p0 = g_parth + (((size_t)(r0 + 16 * mi)     * S_SPLIT + s) << 6) + col;
                    __half* p1 = g_parth + (((size_t)(r0 + 16 * mi + 8) * S_SPLIT + s) << 6) + col;
                    *reinterpret_cast<__half2*>(p0) = __floats2half2_rn(a4[0], a4[1]);
                    *reinterpret_cast<__half2*>(p1) = __floats2half2_rn(a4[2], a4[3]);
                }
            }
        }
    }
}

// ============================================================================
// Kernel 0: finalize norms ONCE.  576 warp-rows: cs[0..511], xs[0..63]
// ============================================================================
__global__ void __launch_bounds__(256)
svm_norm_kernel() {
    const int row  = blockIdx.x * 8 + (threadIdx.x >> 5);   // grid 72 -> 576
    const int lane = threadIdx.x & 31;
    const float* src = (row < NCPAD) ? (g_csq_p + (size_t)row * S_SPLIT)
                                     : (g_xsq_p + (size_t)(row - NCPAD) * S_SPLIT);
    const float4* s4 = reinterpret_cast<const float4*>(src);
    float4 a = s4[lane], b = s4[lane + 32];
    float v = warp_sum(a.x + a.y + a.z + a.w + b.x + b.y + b.z + b.w);
    if (lane == 0) {
        if (row < NCPAD) { if (row < 500) g_cs[row] = v; }
        else             g_xs[row - NCPAD] = v;
    }
}

// ============================================================================
// Kernel 2: coalesced partial reduction + norm lookups -> rbf[b][c]
// ============================================================================
__global__ void __launch_bounds__(512)
svm_rbf_kernel() {
    __shared__ float red[16][NB];
    const int c   = blockIdx.x;          // 0..499
    const int tid = threadIdx.x;         // 512
    const int sp   = tid >> 5;           // 0..15 (16 s-values each)
    const int lane = tid & 31;

    {
        const __half2* p =
            reinterpret_cast<const __half2*>(g_parth + ((size_t)c * S_SPLIT + sp * 16) * NB) + lane;
        float2 a = make_float2(0.f, 0.f);
        #pragma unroll
        for (int i = 0; i < 16; i++) {
            float2 f = __half22float2(p[(size_t)i * 32]);
            a.x += f.x; a.y += f.y;
        }
        red[sp][2 * lane]     = a.x;
        red[sp][2 * lane + 1] = a.y;
    }
    __syncthreads();
    if (tid < NB) {
        float cross = 0.f;
        #pragma unroll
        for (int i = 0; i < 16; i++) cross += red[i][tid];
        float dist = g_xs[tid] - 2.0f * cross + g_cs[c];
        g_rbf[(size_t)tid * NCPAD + c] = expf(-GAMMA_F * dist);   // [b][c]
    }
}

// ============================================================================
// Kernel 3: out[b][i] = sum_c rbf[b][c] * fc_w[i][c] + fc_b[i]
// ============================================================================
__global__ void __launch_bounds__(128)
svm_fc_kernel(const float* __restrict__ fc_w,
              const float* __restrict__ fc_b,
              float* __restrict__ out) {
    __shared__ float w4[4];
    const int b = blockIdx.x >> 3;
    const int i = blockIdx.x & 7;
    const int t = threadIdx.x;
    const float* rr = g_rbf + (size_t)b * NCPAD;
    const float* ww = fc_w + i * 500;
    float acc = 0.f;
    #pragma unroll
    for (int q = 0; q < 4; q++) {
        int c = t + q * 128;
        if (c < 500) acc += rr[c] * ww[c];
    }
    acc = warp_sum(acc);
    if ((t & 31) == 0) w4[t >> 5] = acc;
    __syncthreads();
    if (t == 0) out[b * 8 + i] = w4[0] + w4[1] + w4[2] + w4[3] + fc_b[i];
}

// ============================================================================
extern "C" void kernel_launch(void* const* d_in, const int* in_sizes, int n_in,
                              void* d_out, int out_size) {
    const float* x       = (const float*)d_in[0];
    const float* centers = (const float*)d_in[1];
    const float* fc_w    = (const float*)d_in[2];
    const float* fc_b    = (const float*)d_in[3];
    float* out = (float*)d_out;

    cudaFuncSetAttribute(svm_main_kernel, cudaFuncAttributeMaxDynamicSharedMemorySize, SMEM_TOTAL);

    svm_main_kernel<<<2 * S_SPLIT, 256, SMEM_TOTAL>>>(x, centers);
    svm_norm_kernel<<<72, 256>>>();
    svm_rbf_kernel<<<500, 512>>>();
    svm_fc_kernel<<<512, 128>>>(fc_w, fc_b, out);
}